// round 6
// baseline (speedup 1.0000x reference)
#include <cuda_runtime.h>
#include <math.h>

// Problem constants (fixed by reference)
constexpr int B = 8, C = 96, G = 64 /*PY*PX*/, J = 17, K = 96;
constexpr int GP = G / 2;       // 32 pose pairs
constexpr int SJ = 33;          // float4 row stride per j (odd -> low LDS conflicts)
constexpr float WIDTH = 128.0f;

constexpr int KPT = 8;          // keypoints per thread
constexpr int KG  = K / KPT;    // 12 k-groups
constexpr int NT  = KG * J;     // 204 threads: tid = kg*17 + j

typedef unsigned long long u64;

__device__ __forceinline__ u64 pk2(float lo, float hi) {
    u64 d; asm("mov.b64 %0, {%1, %2};" : "=l"(d) : "f"(lo), "f"(hi)); return d;
}
__device__ __forceinline__ void upk2(float& lo, float& hi, u64 v) {
    asm("mov.b64 {%0, %1}, %2;" : "=f"(lo), "=f"(hi) : "l"(v));
}
__device__ __forceinline__ u64 add2(u64 a, u64 b) {
    u64 d; asm("add.rn.f32x2 %0, %1, %2;" : "=l"(d) : "l"(a), "l"(b)); return d;
}
__device__ __forceinline__ u64 mul2(u64 a, u64 b) {
    u64 d; asm("mul.rn.f32x2 %0, %1, %2;" : "=l"(d) : "l"(a), "l"(b)); return d;
}
__device__ __forceinline__ u64 fma2(u64 a, u64 b, u64 c) {
    u64 d; asm("fma.rn.f32x2 %0, %1, %2, %3;" : "=l"(d) : "l"(a), "l"(b), "l"(c)); return d;
}

__global__ __launch_bounds__(NT, 5)   // 5 blocks/SM -> capacity 740 ~ grid 768 (tiny tail)
void oks_assign_kernel(const float* __restrict__ pose_pool,   // [B,C,8,8,J,2]
                       const float* __restrict__ keypoints,   // [B,K,J,3]
                       const float* __restrict__ areas,       // [B,K]
                       const float* __restrict__ transforms,  // [B,3,3]
                       const float* __restrict__ tinv,        // [B,3,3]
                       const int*   __restrict__ hflip,       // [B]
                       const float* __restrict__ sigmas,      // [J]
                       float* __restrict__ out)
{
    __shared__ float4 posep_sh[J * SJ];      // (x_g0,x_g1,y_g0,y_g1) per (j, g-pair)
    __shared__ float  vis_sum_sh[K];
    __shared__ float  best_sh[K * 18];       // [k][j] padded; reused as parts[G*J]
    __shared__ float  person_sh[K];
    __shared__ int    ks_sh;

    const int bc  = blockIdx.x;
    const int b   = bc / C;
    const int tid = threadIdx.x;
    const int j   = tid % J;      // NT is a multiple of J -> invariant across strides
    const int q   = tid / J;      // 0..KG-1

    // ---- Setup: inverse-affine + hflip; store pose pairs (g0,g1) per lane ----
    {
        const float* Ti = tinv + b * 9;
        const float ti00 = Ti[0], ti01 = Ti[1], ti02 = Ti[2];
        const float ti10 = Ti[3], ti11 = Ti[4], ti12 = Ti[5];
        const bool flipL = hflip[b] > 0;

        const float2* pp = reinterpret_cast<const float2*>(pose_pool) + (size_t)bc * (G * J);
        for (int gp = q; gp < GP; gp += KG) {          // j fixed, walk pairs
            float2 a = pp[(2 * gp) * J + j];
            float2 c = pp[(2 * gp + 1) * J + j];
            float ax = flipL ? (WIDTH - 1.0f - a.x) : a.x;
            float cx = flipL ? (WIDTH - 1.0f - c.x) : c.x;
            float ay = a.y, cy = c.y;
            float x0 = ax * ti00 + ay * ti01 + ti02;
            float y0 = ax * ti10 + ay * ti11 + ti12;
            float x1 = cx * ti00 + cy * ti01 + ti02;
            float y1 = cx * ti10 + cy * ti11 + ti12;
            posep_sh[j * SJ + gp] = make_float4(x0, x1, y0, y1);
        }
    }

    const float* kb = keypoints + (size_t)b * K * J * 3;
    if (tid < K) {
        const float* kp = kb + (size_t)tid * J * 3;
        float s = 0.0f;
        #pragma unroll
        for (int jj = 0; jj < J; jj++) s += (kp[jj * 3 + 2] > 0.0f) ? 1.0f : 0.0f;
        vis_sum_sh[tid] = fmaxf(s, 1.0f);
    }
    __syncthreads();

    // ---- Pass A: min_g d^2 for (my j, my 8 k's), two g's per packed op ----
    const int k0 = q * KPT;

    u64   nkx[KPT], nky[KPT];
    float mind[KPT];
    #pragma unroll
    for (int i = 0; i < KPT; i++) {
        const float* kp = kb + (size_t)(k0 + i) * J * 3 + j * 3;
        float nx = -kp[0];
        float ny = -kp[1];
        nkx[i] = pk2(nx, nx);
        nky[i] = pk2(ny, ny);
        mind[i] = 3.402823466e+38f;
    }

    const float4* prow = posep_sh + j * SJ;
    #pragma unroll 8
    for (int gp = 0; gp < GP; gp++) {
        float4 p4 = prow[gp];               // LDS.128: (x0,x1,y0,y1)
        u64 pxp = pk2(p4.x, p4.y);          // adjacent reg pair
        u64 pyp = pk2(p4.z, p4.w);
        #pragma unroll
        for (int i = 0; i < KPT; i++) {
            u64 dx = add2(pxp, nkx[i]);     // lanewise == scalar FADD
            u64 dy = add2(pyp, nky[i]);
            u64 s  = mul2(dy, dy);
            u64 d  = fma2(dx, dx, s);       // lanewise == scalar FFMA
            float dlo, dhi;
            upk2(dlo, dhi, d);
            mind[i] = fminf(mind[i], dlo);
            mind[i] = fminf(mind[i], dhi);  // 8 independent chains across i
        }
    }

    // best[k][j] = vis * exp(-min_d / denom)   (accurate expf: feeds argmax)
    {
        float sj   = sigmas[j] * 2.0f;
        float varj = sj * sj;
        #pragma unroll
        for (int i = 0; i < KPT; i++) {
            int k = k0 + i;
            float v     = (kb[(size_t)k * J * 3 + j * 3 + 2] > 0.0f) ? 1.0f : 0.0f;
            float denom = fmaxf(2.0f * varj * areas[b * K + k], 1e-6f);
            best_sh[k * 18 + j] = v * expf(-mind[i] / denom);
        }
    }
    __syncthreads();

    // person_best[k] = sum_j best / vis_sum
    if (tid < K) {
        float s = 0.0f;
        #pragma unroll
        for (int jj = 0; jj < J; jj++) s += best_sh[tid * 18 + jj];
        person_sh[tid] = s / vis_sum_sh[tid];
    }
    __syncthreads();

    // Warp-parallel argmax over K (first max wins, matching jnp.argmax)
    if (tid < 32) {
        float bv = -1.0f; int bi = 0;
        #pragma unroll
        for (int r = 0; r < 3; r++) {          // k = tid, tid+32, tid+64 (ascending)
            int k = tid + r * 32;
            float v = person_sh[k];
            if (v > bv) { bv = v; bi = k; }
        }
        #pragma unroll
        for (int off = 16; off > 0; off >>= 1) {
            float ov = __shfl_xor_sync(0xFFFFFFFFu, bv, off);
            int   oi = __shfl_xor_sync(0xFFFFFFFFu, bi, off);
            if (ov > bv || (ov == bv && oi < bi)) { bv = ov; bi = oi; }
        }
        if (tid == 0) ks_sh = bi;
    }
    __syncthreads();
    const int ks = ks_sh;

    // ---- Pass B: outputs for the assigned GT ks ----
    const float  area_s = areas[b * K + ks];
    const float* kpsel  = kb + (size_t)ks * J * 3;
    const bool   flip   = hflip[b] > 0;
    float* parts = best_sh;  // reuse (all best_sh readers synced above)

    float* out_parts  = out;
    float* out_person = out + (size_t)B * C * G * J;
    float* out_posegt = out_person + (size_t)B * C * G;

    {   // j invariant: hoist everything but the pose fetch
        float kxx = kpsel[j * 3 + 0];
        float kyy = kpsel[j * 3 + 1];
        float v   = (kpsel[j * 3 + 2] > 0.0f) ? 1.0f : 0.0f;
        float s2  = sigmas[j] * 2.0f;
        float rdenom = -1.0f / fmaxf(2.0f * s2 * s2 * area_s, 1e-6f);
        float* op = out_parts + (size_t)bc * (G * J);
        #pragma unroll
        for (int g = q; g < G; g += KG) {      // 5-6 iterations
            float4 f4 = posep_sh[j * SJ + (g >> 1)];
            float px = (g & 1) ? f4.y : f4.x;
            float py = (g & 1) ? f4.w : f4.z;
            float dx = px - kxx, dy = py - kyy;
            // __expf: ~2e-6 rel err, only feeds outputs (1e-3 tol), not the argmax
            float oks = v * __expf(fmaf(dx, dx, dy * dy) * rdenom);
            parts[g * J + j] = oks;
            op[g * J + j] = oks;
        }
    }
    __syncthreads();

    if (tid < G) {
        float s = 0.0f;
        #pragma unroll
        for (int jj = 0; jj < J; jj++) s += parts[tid * J + jj];
        out_person[(size_t)bc * G + tid] = s / vis_sum_sh[ks];
    }

    if (tid < J) {
        const float* t = transforms + b * 9;
        float kxx = kpsel[tid * 3 + 0];
        float kyy = kpsel[tid * 3 + 1];
        float kvv = kpsel[tid * 3 + 2];
        float gx = t[0] * kxx + t[1] * kyy + t[2];
        float gy = t[3] * kxx + t[4] * kyy + t[5];
        if (flip) gx = WIDTH - 1.0f - gx;
        float s2 = sigmas[tid] * 2.0f;
        float gv = (t[0] * t[4]) * (area_s * s2 * s2) * ((kvv > 0.0f) ? 1.0f : 0.0f);
        float* og = out_posegt + ((size_t)bc * J + tid) * 3;
        og[0] = gx; og[1] = gy; og[2] = gv;
    }
}

extern "C" void kernel_launch(void* const* d_in, const int* in_sizes, int n_in,
                              void* d_out, int out_size)
{
    const float* pose_pool  = (const float*)d_in[0];
    const float* keypoints  = (const float*)d_in[1];
    const float* areas      = (const float*)d_in[2];
    const float* transforms = (const float*)d_in[3];
    const float* tinv       = (const float*)d_in[4];
    const int*   hflip      = (const int*)  d_in[5];
    const float* sigmas     = (const float*)d_in[6];
    float* out = (float*)d_out;

    oks_assign_kernel<<<B * C, NT>>>(pose_pool, keypoints, areas, transforms,
                                     tinv, hflip, sigmas, out);
}

// round 9
// speedup vs baseline: 1.0906x; 1.0906x over previous
#include <cuda_runtime.h>
#include <math.h>

// Problem constants (fixed by reference)
constexpr int B = 8, C = 96, G = 64 /*PY*PX*/, J = 17, K = 96;
constexpr int GP = G / 2;       // 32 pose pairs
constexpr int SJ = 33;          // float4 row stride per j (odd -> low LDS conflicts)
constexpr float WIDTH = 128.0f;

constexpr int KPT = 6;          // keypoints per thread
constexpr int KG  = K / KPT;    // 16 k-groups
constexpr int NT  = KG * J;     // 272 threads: tid = kg*17 + j

typedef unsigned long long u64;

__device__ __forceinline__ u64 pk2(float lo, float hi) {
    u64 d; asm("mov.b64 %0, {%1, %2};" : "=l"(d) : "f"(lo), "f"(hi)); return d;
}
__device__ __forceinline__ void upk2(float& lo, float& hi, u64 v) {
    asm("mov.b64 {%0, %1}, %2;" : "=f"(lo), "=f"(hi) : "l"(v));
}
__device__ __forceinline__ u64 add2(u64 a, u64 b) {
    u64 d; asm("add.rn.f32x2 %0, %1, %2;" : "=l"(d) : "l"(a), "l"(b)); return d;
}
__device__ __forceinline__ u64 mul2(u64 a, u64 b) {
    u64 d; asm("mul.rn.f32x2 %0, %1, %2;" : "=l"(d) : "l"(a), "l"(b)); return d;
}
__device__ __forceinline__ u64 fma2(u64 a, u64 b, u64 c) {
    u64 d; asm("fma.rn.f32x2 %0, %1, %2, %3;" : "=l"(d) : "l"(a), "l"(b), "l"(c)); return d;
}

__global__ __launch_bounds__(NT, 5)   // <=45 regs target: 5 blocks/SM, capacity 740 ~ grid 768
void oks_assign_kernel(const float* __restrict__ pose_pool,   // [B,C,8,8,J,2]
                       const float* __restrict__ keypoints,   // [B,K,J,3]
                       const float* __restrict__ areas,       // [B,K]
                       const float* __restrict__ transforms,  // [B,3,3]
                       const float* __restrict__ tinv,        // [B,3,3]
                       const int*   __restrict__ hflip,       // [B]
                       const float* __restrict__ sigmas,      // [J]
                       float* __restrict__ out)
{
    __shared__ float4 posep_sh[J * SJ];      // (x_g0,x_g1,y_g0,y_g1) per (j, g-pair)
    __shared__ float  vis_sum_sh[K];
    __shared__ float  best_sh[K * 18];       // [k][j] padded; reused as parts[G*J]
    __shared__ float  person_sh[K];
    __shared__ int    ks_sh;

    const int bc  = blockIdx.x;
    const int b   = bc / C;
    const int tid = threadIdx.x;

    // ---- Setup: inverse-affine + hflip; store pose pairs (g0,g1) per lane ----
    {
        const float* Ti = tinv + b * 9;
        const float ti00 = Ti[0], ti01 = Ti[1], ti02 = Ti[2];
        const float ti10 = Ti[3], ti11 = Ti[4], ti12 = Ti[5];
        const bool flipL = hflip[b] > 0;

        const float2* pp = reinterpret_cast<const float2*>(pose_pool) + (size_t)bc * (G * J);
        for (int idx = tid; idx < J * GP; idx += NT) {
            int gp = idx / J;
            int j  = idx % J;
            float2 a = pp[(2 * gp) * J + j];
            float2 c = pp[(2 * gp + 1) * J + j];
            float ax = flipL ? (WIDTH - 1.0f - a.x) : a.x;
            float cx = flipL ? (WIDTH - 1.0f - c.x) : c.x;
            float ay = a.y, cy = c.y;
            float x0 = ax * ti00 + ay * ti01 + ti02;
            float y0 = ax * ti10 + ay * ti11 + ti12;
            float x1 = cx * ti00 + cy * ti01 + ti02;
            float y1 = cx * ti10 + cy * ti11 + ti12;
            posep_sh[j * SJ + gp] = make_float4(x0, x1, y0, y1);
        }
    }

    const float* kb = keypoints + (size_t)b * K * J * 3;
    if (tid < K) {
        const float* kp = kb + (size_t)tid * J * 3;
        float s = 0.0f;
        #pragma unroll
        for (int jj = 0; jj < J; jj++) s += (kp[jj * 3 + 2] > 0.0f) ? 1.0f : 0.0f;
        vis_sum_sh[tid] = fmaxf(s, 1.0f);
    }
    __syncthreads();

    // ---- Pass A: min_g d^2 for (my j, my 6 k's), two g's per packed op ----
    const int j  = tid % J;
    const int kg = tid / J;
    const int k0 = kg * KPT;

    u64   nkx[KPT], nky[KPT];
    float mind[KPT];
    int   vbits = 0;                        // packed visibility flags (frees 6 LDGs later)
    #pragma unroll
    for (int i = 0; i < KPT; i++) {
        const float* kp = kb + (size_t)(k0 + i) * J * 3 + j * 3;
        float nx = -kp[0];
        float ny = -kp[1];
        if (kp[2] > 0.0f) vbits |= (1 << i);
        nkx[i] = pk2(nx, nx);
        nky[i] = pk2(ny, ny);
        mind[i] = 3.402823466e+38f;
    }

    const float4* prow = posep_sh + j * SJ;
    #pragma unroll 4
    for (int gp = 0; gp < GP; gp++) {
        float4 p4 = prow[gp];               // LDS.128: (x0,x1,y0,y1)
        u64 pxp = pk2(p4.x, p4.y);          // adjacent reg pair
        u64 pyp = pk2(p4.z, p4.w);
        #pragma unroll
        for (int i = 0; i < KPT; i++) {
            u64 dx = add2(pxp, nkx[i]);     // lanewise == scalar FADD
            u64 dy = add2(pyp, nky[i]);
            u64 s  = mul2(dy, dy);
            u64 d  = fma2(dx, dx, s);       // lanewise == scalar FFMA
            float dlo, dhi;
            upk2(dlo, dhi, d);
            mind[i] = fminf(mind[i], dlo);
            mind[i] = fminf(mind[i], dhi);  // 6 independent chains across i
        }
    }

    // best[k][j] = vis * exp(-min_d / denom)   (accurate expf: feeds argmax)
    {
        float sj   = sigmas[j] * 2.0f;
        float varj = sj * sj;
        #pragma unroll
        for (int i = 0; i < KPT; i++) {
            int k = k0 + i;
            float v     = (vbits >> i) & 1 ? 1.0f : 0.0f;
            float denom = fmaxf(2.0f * varj * areas[b * K + k], 1e-6f);
            best_sh[k * 18 + j] = v * expf(-mind[i] / denom);
        }
    }
    __syncthreads();

    // person_best[k] = sum_j best / vis_sum
    if (tid < K) {
        float s = 0.0f;
        #pragma unroll
        for (int jj = 0; jj < J; jj++) s += best_sh[tid * 18 + jj];
        person_sh[tid] = s / vis_sum_sh[tid];
    }
    __syncthreads();

    // Warp-parallel argmax over K (first max wins, matching jnp.argmax)
    if (tid < 32) {
        float bv = -1.0f; int bi = 0;
        #pragma unroll
        for (int r = 0; r < 3; r++) {          // k = tid, tid+32, tid+64 (ascending)
            int k = tid + r * 32;
            float v = person_sh[k];
            if (v > bv) { bv = v; bi = k; }
        }
        #pragma unroll
        for (int off = 16; off > 0; off >>= 1) {
            float ov = __shfl_xor_sync(0xFFFFFFFFu, bv, off);
            int   oi = __shfl_xor_sync(0xFFFFFFFFu, bi, off);
            if (ov > bv || (ov == bv && oi < bi)) { bv = ov; bi = oi; }
        }
        if (tid == 0) ks_sh = bi;
    }
    __syncthreads();
    const int ks = ks_sh;

    // ---- Pass B: outputs for the assigned GT ks ----
    const float  area_s = areas[b * K + ks];
    const float* kpsel  = kb + (size_t)ks * J * 3;
    const bool   flip   = hflip[b] > 0;
    float* parts = best_sh;  // reuse (all best_sh readers synced above)

    float* out_parts  = out;
    float* out_person = out + (size_t)B * C * G * J;
    float* out_posegt = out_person + (size_t)B * C * G;

    {   // j invariant under stride NT (NT % J == 0): hoist per-j state
        float kxx = kpsel[j * 3 + 0];
        float kyy = kpsel[j * 3 + 1];
        float v   = (kpsel[j * 3 + 2] > 0.0f) ? 1.0f : 0.0f;
        float s2  = sigmas[j] * 2.0f;
        float rdenom = -1.0f / fmaxf(2.0f * s2 * s2 * area_s, 1e-6f);
        float* op = out_parts + (size_t)bc * (G * J);
        #pragma unroll
        for (int g = kg; g < G; g += KG) {     // 4 iterations (G/KG = 4)
            float4 f4 = posep_sh[j * SJ + (g >> 1)];
            float px = (g & 1) ? f4.y : f4.x;
            float py = (g & 1) ? f4.w : f4.z;
            float dx = px - kxx, dy = py - kyy;
            // __expf: ~2e-6 rel err, only feeds outputs (1e-3 tol), not the argmax
            float oks = v * __expf(fmaf(dx, dx, dy * dy) * rdenom);
            parts[g * J + j] = oks;
            op[g * J + j] = oks;
        }
    }
    __syncthreads();

    if (tid < G) {
        float s = 0.0f;
        #pragma unroll
        for (int jj = 0; jj < J; jj++) s += parts[tid * J + jj];
        out_person[(size_t)bc * G + tid] = s / vis_sum_sh[ks];
    }

    if (tid < J) {
        const float* t = transforms + b * 9;
        float kxx = kpsel[tid * 3 + 0];
        float kyy = kpsel[tid * 3 + 1];
        float kvv = kpsel[tid * 3 + 2];
        float gx = t[0] * kxx + t[1] * kyy + t[2];
        float gy = t[3] * kxx + t[4] * kyy + t[5];
        if (flip) gx = WIDTH - 1.0f - gx;
        float s2 = sigmas[tid] * 2.0f;
        float gv = (t[0] * t[4]) * (area_s * s2 * s2) * ((kvv > 0.0f) ? 1.0f : 0.0f);
        float* og = out_posegt + ((size_t)bc * J + tid) * 3;
        og[0] = gx; og[1] = gy; og[2] = gv;
    }
}

extern "C" void kernel_launch(void* const* d_in, const int* in_sizes, int n_in,
                              void* d_out, int out_size)
{
    const float* pose_pool  = (const float*)d_in[0];
    const float* keypoints  = (const float*)d_in[1];
    const float* areas      = (const float*)d_in[2];
    const float* transforms = (const float*)d_in[3];
    const float* tinv       = (const float*)d_in[4];
    const int*   hflip      = (const int*)  d_in[5];
    const float* sigmas     = (const float*)d_in[6];
    float* out = (float*)d_out;

    oks_assign_kernel<<<B * C, NT>>>(pose_pool, keypoints, areas, transforms,
                                     tinv, hflip, sigmas, out);
}